// round 1
// baseline (speedup 1.0000x reference)
#include <cuda_runtime.h>
#include <cuda_fp16.h>
#include <cstdint>

// ---------------------------------------------------------------------------
// TensoRF-style NeRF renderer.
//  rgb_map[r] = sum_s w[s] * sigmoid( W3^T relu( W2^T relu( W1^T mlp_in[s] + b1 ) + b2 ) + b3 )
//  mlp_in = [app(27), view(3), PE6(app)(324), PE6(view)(36)]  (K=390, padded to 400)
//  w[s] from alpha-compositing scan of softplus density.
//
// Strategy: persistent CTAs (1/SM), all weights fp16-resident in smem,
// mma.sync m16n8k16 fp16 GEMMs, K-permuted layout pairing sin/cos columns,
// double-angle recurrence for the positional encoding.
// ---------------------------------------------------------------------------

#define S         128
#define NTHREADS  512

#define STRIDE_W1 136     // halves; 272B rows: 16B aligned, conflict-free ldmatrix
#define STRIDE_W2 136
#define STRIDE_H  136
#define STRIDE_IN 120     // max chunk len 112
#define STRIDE_W3 8

// smem offsets (bytes)
#define OFF_W1    0
#define OFF_W2    (OFF_W1 + 400*STRIDE_W1*2)     // 108800
#define OFF_W3    (OFF_W2 + 128*STRIDE_W2*2)     // 143616
#define OFF_IN    (OFF_W3 + 128*STRIDE_W3*2)     // 145664
#define OFF_H     (OFF_IN + 128*STRIDE_IN*2)     // 176384
#define OFF_APP   (OFF_H  + 128*STRIDE_H*2)      // 211200
#define OFF_VIEW  (OFF_APP + 128*27*4)           // 225024
#define OFF_SIG   (OFF_VIEW + 128*3*4)           // 226560
#define OFF_DIST  (OFF_SIG  + 128*4)             // 227072
#define OFF_ALPHA (OFF_DIST + 128*4)             // 227584
#define OFF_WGT   (OFF_ALPHA + 128*4)            // 228096
#define OFF_B1    (OFF_WGT  + 128*4)             // 228608
#define OFF_B2    (OFF_B1   + 128*4)             // 229120
#define OFF_B3    (OFF_B2   + 128*4)             // 229632
#define OFF_ACC   (OFF_B3   + 16)                // 229648
#define SMEM_BYTES (OFF_ACC + 16)                // 229664  (<= 232448)
#define OFF_RGB   OFF_IN   // sIn is dead after layer2; reuse for rgb [128][4] f32

// ---------------------------------------------------------------------------

__device__ __forceinline__ uint32_t smem_u32(const void* p) {
    return (uint32_t)__cvta_generic_to_shared(p);
}
__device__ __forceinline__ void ldmA4(uint32_t a[4], uint32_t addr) {
    asm volatile("ldmatrix.sync.aligned.m8n8.x4.shared.b16 {%0,%1,%2,%3}, [%4];"
                 : "=r"(a[0]), "=r"(a[1]), "=r"(a[2]), "=r"(a[3]) : "r"(addr));
}
__device__ __forceinline__ void ldmBT4(uint32_t b[4], uint32_t addr) {
    asm volatile("ldmatrix.sync.aligned.m8n8.x4.trans.shared.b16 {%0,%1,%2,%3}, [%4];"
                 : "=r"(b[0]), "=r"(b[1]), "=r"(b[2]), "=r"(b[3]) : "r"(addr));
}
__device__ __forceinline__ void ldmBT2(uint32_t b[2], uint32_t addr) {
    asm volatile("ldmatrix.sync.aligned.m8n8.x2.trans.shared.b16 {%0,%1}, [%2];"
                 : "=r"(b[0]), "=r"(b[1]) : "r"(addr));
}
__device__ __forceinline__ void mma16816(float c[4], const uint32_t a[4],
                                         uint32_t b0, uint32_t b1) {
    asm volatile("mma.sync.aligned.m16n8k16.row.col.f32.f16.f16.f32 "
                 "{%0,%1,%2,%3}, {%4,%5,%6,%7}, {%8,%9}, {%0,%1,%2,%3};"
                 : "+f"(c[0]), "+f"(c[1]), "+f"(c[2]), "+f"(c[3])
                 : "r"(a[0]), "r"(a[1]), "r"(a[2]), "r"(a[3]), "r"(b0), "r"(b1));
}
__device__ __forceinline__ float sigmoidf_(float x) {
    return 1.0f / (1.0f + __expf(-x));
}

// Our K permutation:
//  k in [0,360):   pair region; channel cc = k/12 (0..26 app, 27..29 view),
//                  f = (k%12)/2, k&1 ? cos : sin   of (x_cc * 2^f)
//  k in [360,387): raw app[k-360]
//  k in [387,390): raw view[k-387]
//  k in [390,400): zero pad
// Original column index in the reference's 390-wide mlp_in:
__device__ __forceinline__ int orig_row(int k) {
    if (k < 360) {
        int cc = k / 12;
        int f  = (k % 12) >> 1;
        int isc = k & 1;
        if (cc < 27) return 30 + cc*6 + f + (isc ? 162 : 0);
        return 354 + (cc - 27)*6 + f + (isc ? 18 : 0);
    }
    if (k < 387) return k - 360;
    if (k < 390) return 27 + (k - 387);
    return -1;
}

// Fill sIn columns [C0*12-KBASE ...) with sin/cos PE via double-angle recurrence.
template<int C0, int NCH, int KBASE>
__device__ __forceinline__ void fill_pairs(char* sm, int tid) {
    const float* sApp  = (const float*)(sm + OFF_APP);
    const float* sView = (const float*)(sm + OFF_VIEW);
    __half* sIn = (__half*)(sm + OFF_IN);
    for (int i = tid; i < 128*NCH; i += NTHREADS) {
        int s  = i / NCH;
        int cc = C0 + (i - s*NCH);
        float x = (cc < 27) ? sApp[s*27 + cc] : sView[s*3 + (cc - 27)];
        float sn, cs;
        __sincosf(x, &sn, &cs);                 // f = 0
        __half2* dst = (__half2*)&sIn[s*STRIDE_IN + (cc*12 - KBASE)];
        #pragma unroll
        for (int f = 0; f < 6; f++) {
            dst[f] = __floats2half2_rn(sn, cs);
            float s2 = 2.0f*sn*cs;              // sin(2x)
            float c2 = 1.0f - 2.0f*sn*sn;       // cos(2x)
            sn = s2; cs = c2;
        }
    }
}

// ---------------------------------------------------------------------------

__global__ void __launch_bounds__(NTHREADS, 1)
nerf_render_kernel(const float* __restrict__ sigma_feat,
                   const float* __restrict__ app,
                   const float* __restrict__ view,
                   const float* __restrict__ dists,
                   const float* __restrict__ W1, const float* __restrict__ b1,
                   const float* __restrict__ W2, const float* __restrict__ b2,
                   const float* __restrict__ W3, const float* __restrict__ b3,
                   float* __restrict__ out, int R)
{
    extern __shared__ char sm[];
    __half* sW1 = (__half*)(sm + OFF_W1);
    __half* sW2 = (__half*)(sm + OFF_W2);
    __half* sW3 = (__half*)(sm + OFF_W3);
    __half* sIn = (__half*)(sm + OFF_IN);
    __half* sH  = (__half*)(sm + OFF_H);
    float* sApp   = (float*)(sm + OFF_APP);
    float* sView  = (float*)(sm + OFF_VIEW);
    float* sSig   = (float*)(sm + OFF_SIG);
    float* sDist  = (float*)(sm + OFF_DIST);
    float* sAlpha = (float*)(sm + OFF_ALPHA);
    float* sWgt   = (float*)(sm + OFF_WGT);
    float* sB1    = (float*)(sm + OFF_B1);
    float* sB2    = (float*)(sm + OFF_B2);
    float* sB3    = (float*)(sm + OFF_B3);
    float* sAcc   = (float*)(sm + OFF_ACC);
    float* sRGB   = (float*)(sm + OFF_RGB);

    const int tid  = threadIdx.x;
    const int lane = tid & 31;
    const int warp = tid >> 5;

    // ---- one-time: weights -> smem (fp16), K-permuted W1 ----
    for (int idx = tid; idx < 400*128; idx += NTHREADS) {
        int k = idx >> 7, n = idx & 127;
        int o = orig_row(k);
        float v = (o >= 0) ? W1[o*128 + n] : 0.0f;
        sW1[k*STRIDE_W1 + n] = __float2half(v);
    }
    for (int idx = tid; idx < 128*128; idx += NTHREADS) {
        int k = idx >> 7, n = idx & 127;
        sW2[k*STRIDE_W2 + n] = __float2half(W2[idx]);
    }
    for (int idx = tid; idx < 128*8; idx += NTHREADS) {
        int k = idx >> 3, n = idx & 7;
        sW3[idx] = __float2half((n < 3) ? W3[k*3 + n] : 0.0f);
    }
    if (tid < 128) { sB1[tid] = b1[tid]; sB2[tid] = b2[tid]; }
    if (tid < 3)   sB3[tid] = b3[tid];

    const int mbase = (warp >> 1) << 4;   // 16-row tile per warp pair
    const int nb0   = (warp & 1) << 6;    // 64-col half
    const int lr    = lane & 15;          // ldmatrix row select
    const int lc8   = (lane >> 4) << 3;   // ldmatrix col half (0/8)

    const uint32_t inBase = smem_u32(sIn);
    const uint32_t w1Base = smem_u32(sW1);
    const uint32_t w2Base = smem_u32(sW2);
    const uint32_t w3Base = smem_u32(sW3);
    const uint32_t hBase  = smem_u32(sH);

    for (int ray = blockIdx.x; ray < R; ray += gridDim.x) {
        __syncthreads();   // protect smem reuse from previous ray

        // ---- stage ray inputs ----
        {
            const float* gA = app  + (size_t)ray * (S*27);
            for (int i = tid; i < S*27; i += NTHREADS) sApp[i] = gA[i];
            const float* gV = view + (size_t)ray * (S*3);
            for (int i = tid; i < S*3; i += NTHREADS) sView[i] = gV[i];
            if (tid < S) {
                sSig[tid]  = sigma_feat[(size_t)ray*S + tid];
                sDist[tid] = dists[(size_t)ray*S + tid];
            }
            if (tid < 4) sAcc[tid] = 0.0f;
        }
        __syncthreads();

        // ---- alpha (parallel) + PE fill chunk 0 ----
        if (tid < S) {
            float x  = sSig[tid] - 10.0f;                      // density_shift
            float sp = (x > 20.0f) ? x : log1pf(__expf(x));    // softplus
            sAlpha[tid] = 1.0f - __expf(-sp * sDist[tid] * 25.0f);
        }
        fill_pairs<0, 8, 0>(sm, tid);
        __syncthreads();

        // serial compositing scan (hidden under other warps' MMA)
        if (tid == 0) {
            float T = 1.0f;
            #pragma unroll 4
            for (int s2 = 0; s2 < S; s2++) {
                float a = (s2 == S-1) ? 1.0f : sAlpha[s2];
                sWgt[s2] = a * T;
                T *= (1.0f - a + 1e-10f);
            }
        }

        // ---- layer 1: [128 x 400] @ [400 x 128], K streamed in 4 chunks ----
        float acc[8][4];
        #pragma unroll
        for (int i = 0; i < 8; i++)
            #pragma unroll
            for (int j = 0; j < 4; j++) acc[i][j] = 0.0f;

        #pragma unroll 1
        for (int ch = 0; ch < 4; ch++) {
            const int kbase = ch * 96;
            const int klen  = (ch == 3) ? 112 : 96;
            for (int kk = 0; kk < klen; kk += 16) {
                uint32_t a[4];
                ldmA4(a, inBase + (uint32_t)(((mbase + lr)*STRIDE_IN + kk + lc8) * 2));
                #pragma unroll
                for (int nt = 0; nt < 8; nt += 2) {
                    uint32_t b[4];
                    ldmBT4(b, w1Base + (uint32_t)(((kbase + kk + lr)*STRIDE_W1
                                                  + nb0 + (nt << 3) + lc8) * 2));
                    mma16816(acc[nt],   a, b[0], b[1]);
                    mma16816(acc[nt+1], a, b[2], b[3]);
                }
            }
            __syncthreads();
            if (ch == 0)      { fill_pairs<8, 8, 96>(sm, tid);  __syncthreads(); }
            else if (ch == 1) { fill_pairs<16, 8, 192>(sm, tid); __syncthreads(); }
            else if (ch == 2) {
                fill_pairs<24, 6, 288>(sm, tid);
                for (int i = tid; i < S*40; i += NTHREADS) {   // raw cols + zero pad
                    int s2 = i / 40, j = i - s2*40;
                    float v = (j < 27) ? sApp[s2*27 + j]
                            : ((j < 30) ? sView[s2*3 + j - 27] : 0.0f);
                    sIn[s2*STRIDE_IN + 72 + j] = __float2half(v);
                }
                __syncthreads();
            }
        }

        // bias + relu -> sH (fp16)
        {
            const int r  = mbase + (lane >> 2);
            const int cb = nb0 + ((lane & 3) << 1);
            #pragma unroll
            for (int nt = 0; nt < 8; nt++) {
                int c = cb + (nt << 3);
                float bb0 = sB1[c], bb1 = sB1[c+1];
                float v0 = fmaxf(acc[nt][0] + bb0, 0.0f);
                float v1 = fmaxf(acc[nt][1] + bb1, 0.0f);
                float v2 = fmaxf(acc[nt][2] + bb0, 0.0f);
                float v3 = fmaxf(acc[nt][3] + bb1, 0.0f);
                *(__half2*)&sH[r*STRIDE_H + c]       = __floats2half2_rn(v0, v1);
                *(__half2*)&sH[(r+8)*STRIDE_H + c]   = __floats2half2_rn(v2, v3);
            }
        }
        __syncthreads();

        // ---- layer 2: [128 x 128] @ [128 x 128] ----
        #pragma unroll
        for (int i = 0; i < 8; i++)
            #pragma unroll
            for (int j = 0; j < 4; j++) acc[i][j] = 0.0f;

        for (int kk = 0; kk < 128; kk += 16) {
            uint32_t a[4];
            ldmA4(a, hBase + (uint32_t)(((mbase + lr)*STRIDE_H + kk + lc8) * 2));
            #pragma unroll
            for (int nt = 0; nt < 8; nt += 2) {
                uint32_t b[4];
                ldmBT4(b, w2Base + (uint32_t)(((kk + lr)*STRIDE_W2
                                              + nb0 + (nt << 3) + lc8) * 2));
                mma16816(acc[nt],   a, b[0], b[1]);
                mma16816(acc[nt+1], a, b[2], b[3]);
            }
        }
        __syncthreads();   // everyone done reading h1 before overwrite

        {
            const int r  = mbase + (lane >> 2);
            const int cb = nb0 + ((lane & 3) << 1);
            #pragma unroll
            for (int nt = 0; nt < 8; nt++) {
                int c = cb + (nt << 3);
                float bb0 = sB2[c], bb1 = sB2[c+1];
                float v0 = fmaxf(acc[nt][0] + bb0, 0.0f);
                float v1 = fmaxf(acc[nt][1] + bb1, 0.0f);
                float v2 = fmaxf(acc[nt][2] + bb0, 0.0f);
                float v3 = fmaxf(acc[nt][3] + bb1, 0.0f);
                *(__half2*)&sH[r*STRIDE_H + c]     = __floats2half2_rn(v0, v1);
                *(__half2*)&sH[(r+8)*STRIDE_H + c] = __floats2half2_rn(v2, v3);
            }
        }
        __syncthreads();

        // ---- layer 3: [128 x 128] @ [128 x 8(pad of 3)] + sigmoid ----
        if (warp < 8) {
            float a3[4] = {0.0f, 0.0f, 0.0f, 0.0f};
            #pragma unroll
            for (int kk = 0; kk < 128; kk += 16) {
                uint32_t a[4];
                ldmA4(a, hBase + (uint32_t)((((warp << 4) + lr)*STRIDE_H + kk + lc8) * 2));
                uint32_t b[2];
                ldmBT2(b, w3Base + (uint32_t)(((kk + lr)*STRIDE_W3) * 2));
                mma16816(a3, a, b[0], b[1]);
            }
            int r = (warp << 4) + (lane >> 2);
            int q = lane & 3;
            if (q == 0) {
                sRGB[r*4 + 0]     = sigmoidf_(a3[0] + sB3[0]);
                sRGB[r*4 + 1]     = sigmoidf_(a3[1] + sB3[1]);
                sRGB[(r+8)*4 + 0] = sigmoidf_(a3[2] + sB3[0]);
                sRGB[(r+8)*4 + 1] = sigmoidf_(a3[3] + sB3[1]);
            } else if (q == 1) {
                sRGB[r*4 + 2]     = sigmoidf_(a3[0] + sB3[2]);
                sRGB[(r+8)*4 + 2] = sigmoidf_(a3[2] + sB3[2]);
            }
        }
        __syncthreads();

        // ---- weighted reduction over samples ----
        if (tid < 384) {
            int c  = tid >> 7;
            int s2 = tid & 127;
            float v = sWgt[s2] * sRGB[s2*4 + c];
            #pragma unroll
            for (int off = 16; off; off >>= 1)
                v += __shfl_down_sync(0xffffffffu, v, off);
            if (lane == 0) atomicAdd(&sAcc[c], v);
        }
        __syncthreads();
        if (tid < 3) out[(size_t)ray*3 + tid] = sAcc[tid];
    }
}

// ---------------------------------------------------------------------------

extern "C" void kernel_launch(void* const* d_in, const int* in_sizes, int n_in,
                              void* d_out, int out_size) {
    const float* sigma_feat = (const float*)d_in[0];
    const float* app        = (const float*)d_in[1];
    const float* viewd      = (const float*)d_in[2];
    const float* dists      = (const float*)d_in[3];
    const float* W1         = (const float*)d_in[4];
    const float* b1         = (const float*)d_in[5];
    const float* W2         = (const float*)d_in[6];
    const float* b2         = (const float*)d_in[7];
    const float* W3         = (const float*)d_in[8];
    const float* b3         = (const float*)d_in[9];
    float* out = (float*)d_out;

    int R = in_sizes[0] / S;   // 4096

    int sms = 0;
    cudaDeviceGetAttribute(&sms, cudaDevAttrMultiProcessorCount, 0);
    if (sms <= 0) sms = 148;
    int grid = sms < R ? sms : R;

    cudaFuncSetAttribute(nerf_render_kernel,
                         cudaFuncAttributeMaxDynamicSharedMemorySize, SMEM_BYTES);

    nerf_render_kernel<<<grid, NTHREADS, SMEM_BYTES>>>(
        sigma_feat, app, viewd, dists, W1, b1, W2, b2, W3, b3, out, R);
}